// round 4
// baseline (speedup 1.0000x reference)
#include <cuda_runtime.h>
#include <cuda_bf16.h>

// LSTM_20452634263894: B=32768, T=512, I=2, H=16.
// One thread per batch element; h/c in registers; gate-pair-packed f32x2 FMAs;
// W_hh pre-packed in shared as (gate 2p, gate 2p+1) pairs per k.

#define B_TOT 32768
#define T_LEN 512
#define I_DIM 2
#define H_DIM 16
#define G_DIM 64   // 4*H
#define NP    32   // gate pairs

__device__ __forceinline__ unsigned long long pack2(float lo, float hi) {
    unsigned long long r;
    asm("mov.b64 %0, {%1, %2};" : "=l"(r) : "f"(lo), "f"(hi));
    return r;
}
__device__ __forceinline__ void unpack2(unsigned long long v, float& lo, float& hi) {
    asm("mov.b64 {%0, %1}, %2;" : "=f"(lo), "=f"(hi) : "l"(v));
}
__device__ __forceinline__ unsigned long long ffma2(unsigned long long a,
                                                    unsigned long long b,
                                                    unsigned long long c) {
    unsigned long long d;
    asm("fma.rn.f32x2 %0, %1, %2, %3;" : "=l"(d) : "l"(a), "l"(b), "l"(c));
    return d;
}
__device__ __forceinline__ float tanh_fast(float x) {
    float y;
    asm("tanh.approx.f32 %0, %1;" : "=f"(y) : "f"(x));
    return y;
}
__device__ __forceinline__ float sigmoid_fast(float x) {
    return fmaf(0.5f, tanh_fast(0.5f * x), 0.5f);
}

__global__ void __launch_bounds__(128, 2) lstm_fused_kernel(
    const float* __restrict__ x,
    const float* __restrict__ W_ih, const float* __restrict__ W_hh,
    const float* __restrict__ b_ih, const float* __restrict__ b_hh,
    const float* __restrict__ W1,  const float* __restrict__ b1,
    const float* __restrict__ W2,  const float* __restrict__ b2,
    float* __restrict__ out)
{
    // Packed weights in shared. sWhh[k][p] = (W_hh[2p][k], W_hh[2p+1][k]).
    __shared__ __align__(16) unsigned long long sWhh[H_DIM][NP];
    __shared__ __align__(16) unsigned long long sWih[2][NP];
    __shared__ __align__(16) unsigned long long sBias[NP];
    __shared__ float sW1[H_DIM * H_DIM];
    __shared__ float sb1[H_DIM];
    __shared__ float sW2[I_DIM * H_DIM];
    __shared__ float sb2[I_DIM];

    const int tid = threadIdx.x;

    for (int idx = tid; idx < H_DIM * NP; idx += blockDim.x) {
        int k = idx / NP, p = idx % NP;
        sWhh[k][p] = pack2(W_hh[(2 * p) * H_DIM + k], W_hh[(2 * p + 1) * H_DIM + k]);
    }
    for (int idx = tid; idx < 2 * NP; idx += blockDim.x) {
        int cc = idx / NP, p = idx % NP;
        sWih[cc][p] = pack2(W_ih[(2 * p) * I_DIM + cc], W_ih[(2 * p + 1) * I_DIM + cc]);
    }
    for (int idx = tid; idx < NP; idx += blockDim.x) {
        sBias[idx] = pack2(b_ih[2 * idx] + b_hh[2 * idx],
                           b_ih[2 * idx + 1] + b_hh[2 * idx + 1]);
    }
    for (int idx = tid; idx < H_DIM * H_DIM; idx += blockDim.x) sW1[idx] = W1[idx];
    for (int idx = tid; idx < H_DIM; idx += blockDim.x) sb1[idx] = b1[idx];
    for (int idx = tid; idx < I_DIM * H_DIM; idx += blockDim.x) sW2[idx] = W2[idx];
    for (int idx = tid; idx < I_DIM; idx += blockDim.x) sb2[idx] = b2[idx];
    __syncthreads();

    const int b = blockIdx.x * blockDim.x + tid;
    const float2* __restrict__ xrow =
        reinterpret_cast<const float2*>(x) + (size_t)b * T_LEN;

    float h[H_DIM], c[H_DIM];
#pragma unroll
    for (int u = 0; u < H_DIM; ++u) { h[u] = 0.0f; c[u] = 0.0f; }

    // Combined bias held in registers (64 regs) — removes per-step bias LDS.
    unsigned long long biasr[NP];
#pragma unroll
    for (int p = 0; p < NP; ++p) biasr[p] = sBias[p];

    const ulonglong2* __restrict__ wih0 =
        reinterpret_cast<const ulonglong2*>(&sWih[0][0]);
    const ulonglong2* __restrict__ wih1 =
        reinterpret_cast<const ulonglong2*>(&sWih[1][0]);

    for (int t = 0; t < T_LEN; ++t) {
        float2 xv = __ldg(xrow + t);
        unsigned long long px0 = pack2(xv.x, xv.x);
        unsigned long long px1 = pack2(xv.y, xv.y);

        unsigned long long acc[NP];
        // acc = bias + x0*Wih[:,0] + x1*Wih[:,1]  (input projection on the fly)
#pragma unroll
        for (int p2 = 0; p2 < NP / 2; ++p2) {
            ulonglong2 w0 = wih0[p2];
            ulonglong2 w1 = wih1[p2];
            acc[2 * p2]     = ffma2(px1, w1.x, ffma2(px0, w0.x, biasr[2 * p2]));
            acc[2 * p2 + 1] = ffma2(px1, w1.y, ffma2(px0, w0.y, biasr[2 * p2 + 1]));
        }
        // Recurrent matvec: acc[p] += h[k] * Whh_pair[k][p]
#pragma unroll
        for (int k = 0; k < H_DIM; ++k) {
            unsigned long long hk = pack2(h[k], h[k]);
            const ulonglong2* __restrict__ row =
                reinterpret_cast<const ulonglong2*>(&sWhh[k][0]);
#pragma unroll
            for (int p2 = 0; p2 < NP / 2; ++p2) {
                ulonglong2 w = row[p2];
                acc[2 * p2]     = ffma2(hk, w.x, acc[2 * p2]);
                acc[2 * p2 + 1] = ffma2(hk, w.y, acc[2 * p2 + 1]);
            }
        }
        // Unpack gates (i, f, g, o in torch order) and update state.
        float g[G_DIM];
#pragma unroll
        for (int p = 0; p < NP; ++p) unpack2(acc[p], g[2 * p], g[2 * p + 1]);
#pragma unroll
        for (int u = 0; u < H_DIM; ++u) {
            float ig = sigmoid_fast(g[u]);
            float fg = sigmoid_fast(g[H_DIM + u]);
            float gg = tanh_fast(g[2 * H_DIM + u]);
            float og = sigmoid_fast(g[3 * H_DIM + u]);
            float cn = fmaf(fg, c[u], ig * gg);
            c[u] = cn;
            h[u] = og * tanh_fast(cn);
        }
    }

    // MLP head: y = tanh(h @ W1^T + b1) @ W2^T + b2
    float y0 = sb2[0], y1 = sb2[1];
#pragma unroll
    for (int j = 0; j < H_DIM; ++j) {
        float z = sb1[j];
#pragma unroll
        for (int k = 0; k < H_DIM; ++k) z = fmaf(h[k], sW1[j * H_DIM + k], z);
        z = tanh_fast(z);
        y0 = fmaf(z, sW2[0 * H_DIM + j], y0);
        y1 = fmaf(z, sW2[1 * H_DIM + j], y1);
    }
    reinterpret_cast<float2*>(out)[b] = make_float2(y0, y1);
}

extern "C" void kernel_launch(void* const* d_in, const int* in_sizes, int n_in,
                              void* d_out, int out_size) {
    const float* x    = (const float*)d_in[0];
    const float* W_ih = (const float*)d_in[1];
    const float* W_hh = (const float*)d_in[2];
    const float* b_ih = (const float*)d_in[3];
    const float* b_hh = (const float*)d_in[4];
    const float* W1   = (const float*)d_in[5];
    const float* b1   = (const float*)d_in[6];
    const float* W2   = (const float*)d_in[7];
    const float* b2   = (const float*)d_in[8];
    float* out = (float*)d_out;

    dim3 block(128);
    dim3 grid(B_TOT / 128);  // 256 CTAs, one thread per batch row
    lstm_fused_kernel<<<grid, block>>>(x, W_ih, W_hh, b_ih, b_hh,
                                       W1, b1, W2, b2, out);
}